// round 5
// baseline (speedup 1.0000x reference)
#include <cuda_runtime.h>
#include <cuda_bf16.h>
#include <cstdint>
#include <math.h>

// ---------------- problem constants ----------------
#define NN 8192
#define INF_ 128
#define OUTF 64

// grid decomposition for k_main
#define M_CTA 256        // rows per CTA
#define NSPLIT 4         // K splits
#define KSPLIT (NN / NSPLIT)   // 2048 cols per CTA
#define KCHUNK 64        // cols per chunk
#define NCHUNK (KSPLIT / KCHUNK) // 32

// ---------------- device scratch (no allocs allowed) ----------------
__device__ float g_h[NN * OUTF];                    // 2 MB   h = X@W
__device__ float4 g_rowf[NN];                       // (f1, e^f1, e^{0.2 f1}, 0)
__device__ float4 g_colf[NN];                       // (f2, e^{f2}, e^{0.2 f2}, 0)
__device__ uint32_t g_Bf[NN * OUTF];                // 2 MB   Ht, tf32 bits, B-fragment order
__device__ float g_num[NSPLIT][NN * OUTF];          // 8 MB   partial numerators
__device__ float g_den[NSPLIT][NN];                 // partial denominators

// ---------------- smem layout for k_main ----------------
#define ADJ_STRIDE 272            // bytes per adj row (64 ints + pad, conflict-free)
#define ADJ_BYTES (M_CTA * ADJ_STRIDE)   // 69632
#define OFF_ADJ0 0
#define OFF_ADJ1 69632
#define OFF_BF0  139264           // 16384 each: [s][f][lane][2] tf32
#define OFF_BF1  155648
#define OFF_CF0  172032           // 1024 each: 64 x float4 col factors
#define OFF_CF1  173056
#define SMEM_BYTES 174080

// ---------------- helpers ----------------
__device__ __forceinline__ uint32_t smem_u32(const void* p) {
    uint32_t a;
    asm("{ .reg .u64 t; cvta.to.shared.u64 t, %1; cvt.u32.u64 %0, t; }" : "=r"(a) : "l"(p));
    return a;
}
#define CP16(dst, src) \
    asm volatile("cp.async.cg.shared.global [%0], [%1], 16;" :: "r"(dst), "l"(src) : "memory")
#define CP_COMMIT() asm volatile("cp.async.commit_group;" ::: "memory")
#define CP_WAIT1()  asm volatile("cp.async.wait_group 1;" ::: "memory")

__device__ __forceinline__ uint32_t f2tf32(float x) {
    uint32_t r;
    asm("cvt.rna.tf32.f32 %0, %1;" : "=r"(r) : "f"(x));
    return r;
}
__device__ __forceinline__ void mma_tf32(float& d0, float& d1, float& d2, float& d3,
                                         uint32_t a0, uint32_t a1, uint32_t a2, uint32_t a3,
                                         uint32_t b0, uint32_t b1) {
    asm volatile("mma.sync.aligned.m16n8k8.row.col.f32.tf32.tf32.f32 "
                 "{%0,%1,%2,%3}, {%4,%5,%6,%7}, {%8,%9}, {%0,%1,%2,%3};"
                 : "+f"(d0), "+f"(d1), "+f"(d2), "+f"(d3)
                 : "r"(a0), "r"(a1), "r"(a2), "r"(a3), "r"(b0), "r"(b1));
}

// ---------------- kernel 1: h = X @ W ----------------
__global__ void __launch_bounds__(256) k_h(const float* __restrict__ X, const float* __restrict__ W) {
    __shared__ float Ws[INF_ * OUTF];
    __shared__ float Xs[32 * INF_];
    int tid = threadIdx.x;
    const float4* W4 = (const float4*)W;
    float4* Ws4 = (float4*)Ws;
#pragma unroll
    for (int q = 0; q < 8; q++) Ws4[tid + q * 256] = W4[tid + q * 256];
    int r0 = blockIdx.x * 32;
    const float4* X4 = (const float4*)(X + (size_t)r0 * INF_);
    float4* Xs4 = (float4*)Xs;
#pragma unroll
    for (int q = 0; q < 4; q++) Xs4[tid + q * 256] = X4[tid + q * 256];
    __syncthreads();
    int r = tid >> 3, cg = (tid & 7) * 8;
    float acc[8];
#pragma unroll
    for (int j = 0; j < 8; j++) acc[j] = 0.f;
#pragma unroll 4
    for (int k = 0; k < INF_; k++) {
        float xv = Xs[r * INF_ + k];
        float4 w0 = *(float4*)&Ws[k * OUTF + cg];
        float4 w1 = *(float4*)&Ws[k * OUTF + cg + 4];
        acc[0] += xv * w0.x; acc[1] += xv * w0.y; acc[2] += xv * w0.z; acc[3] += xv * w0.w;
        acc[4] += xv * w1.x; acc[5] += xv * w1.y; acc[6] += xv * w1.z; acc[7] += xv * w1.w;
    }
    float* out = g_h + (size_t)(r0 + r) * OUTF + cg;
    *(float4*)out = make_float4(acc[0], acc[1], acc[2], acc[3]);
    *(float4*)(out + 4) = make_float4(acc[4], acc[5], acc[6], acc[7]);
}

// ---------------- kernel 2: per-node factors ----------------
__global__ void __launch_bounds__(256) k_f(const float* __restrict__ a) {
    int row = blockIdx.x * 8 + (threadIdx.x >> 5);
    int lane = threadIdx.x & 31;
    const float* hr = g_h + (size_t)row * OUTF;
    float s1 = hr[lane] * a[lane] + hr[lane + 32] * a[lane + 32];
    float s2 = hr[lane] * a[64 + lane] + hr[lane + 32] * a[96 + lane];
#pragma unroll
    for (int o = 16; o > 0; o >>= 1) {
        s1 += __shfl_xor_sync(0xFFFFFFFF, s1, o);
        s2 += __shfl_xor_sync(0xFFFFFFFF, s2, o);
    }
    if (lane == 0) {
        g_rowf[row] = make_float4(s1, expf(s1), expf(0.2f * s1), 0.f);
        g_colf[row] = make_float4(s2, expf(s2), expf(0.2f * s2), 0.f);
    }
}

// ---------------- kernel 3: B fragments (Ht -> tf32, m16n8k8 b-frag order) ----------------
// b0 of lane l, kstep s, nfrag f = h[8s + (l&3)][8f + (l>>2)], b1 = h[8s+(l&3)+4][...]
// layout: g_Bf[ ((s*8 + f)*32 + l)*2 + half ]
__global__ void __launch_bounds__(256) k_bf() {
    int idx = blockIdx.x * 256 + threadIdx.x;   // over NN*OUTF
    int j = idx >> 6;     // node
    int n = idx & 63;     // feat
    float v = g_h[(size_t)j * OUTF + n];
    int s = j >> 3;
    int f = n >> 3;
    int l = ((n & 7) << 2) | (j & 3);
    int half = (j >> 2) & 1;
    g_Bf[(((size_t)(s * 8 + f) * 32 + l) << 1) + half] = f2tf32(v);
}

// ---------------- main kernel ----------------
// grid 128: rb = blockIdx & 31 (row block of 256), split = blockIdx >> 5
__global__ void __launch_bounds__(256, 1) k_main(const int* __restrict__ adj) {
    extern __shared__ char sm[];
    uint32_t sb = smem_u32(sm);

    int tid = threadIdx.x;
    int wid = tid >> 5;
    int lane = tid & 31;
    int g = lane >> 2;
    int c = lane & 3;

    int rb = blockIdx.x & 31;
    int split = blockIdx.x >> 5;
    int row0 = rb * M_CTA;
    int K0base = split * KSPLIT;

    // hoist row factors for this thread's 4 rows (g, g+8, g+16, g+24 within warp's 32)
    float f1r[4], e1r[4], e1br[4];
#pragma unroll
    for (int q = 0; q < 4; q++) {
        float4 rf = g_rowf[row0 + wid * 32 + g + q * 8];
        f1r[q] = rf.x; e1r[q] = rf.y; e1br[q] = rf.z;
    }

    // accumulators: [rowfrag 2][nfrag 8][4]
    float acc[2][8][4];
#pragma unroll
    for (int i = 0; i < 2; i++)
#pragma unroll
        for (int f = 0; f < 8; f++)
#pragma unroll
            for (int q = 0; q < 4; q++) acc[i][f][q] = 0.f;

    float den[4] = {0.f, 0.f, 0.f, 0.f};

    const uint32_t adjOff[2] = {OFF_ADJ0, OFF_ADJ1};
    const uint32_t bfOff[2] = {OFF_BF0, OFF_BF1};
    const uint32_t cfOff[2] = {OFF_CF0, OFF_CF1};

    // ---- prefetch helper ----
    auto prefetch = [&](int chunk, int buf) {
        int K0 = K0base + chunk * KCHUNK;
        // adj: 256 rows x 64 ints
        int jr = tid & 15;
        int rbase = tid >> 4;
        const char* srcbase = (const char*)(adj + (size_t)row0 * NN + K0) + jr * 16;
        uint32_t dstbase = sb + adjOff[buf] + jr * 16;
#pragma unroll
        for (int pass = 0; pass < 16; pass++) {
            int row = pass * 16 + rbase;
            CP16(dstbase + row * ADJ_STRIDE, srcbase + (size_t)row * (NN * 4));
        }
        // B fragments: 16 KB contiguous at g_Bf byte offset K0*256
        const char* bsrc = (const char*)g_Bf + (size_t)K0 * 256;
        uint32_t bdst = sb + bfOff[buf];
#pragma unroll
        for (int p = 0; p < 4; p++) {
            int piece = tid + p * 256;
            CP16(bdst + piece * 16, bsrc + piece * 16);
        }
        // col factors: 64 x float4
        if (tid < 64) {
            CP16(sb + cfOff[buf] + tid * 16, (const char*)(g_colf + K0 + tid));
        }
    };

    prefetch(0, 0); CP_COMMIT();
    prefetch(1, 1); CP_COMMIT();

    for (int it = 0; it < NCHUNK; ++it) {
        int buf = it & 1;
        CP_WAIT1();
        __syncthreads();

        const char* adjS = sm + adjOff[buf];
        const uint32_t* bS = (const uint32_t*)(sm + bfOff[buf]);
        const float4* cfS = (const float4*)(sm + cfOff[buf]);

#pragma unroll
        for (int s = 0; s < 8; s++) {
            float4 c0 = cfS[s * 8 + c];
            float4 c4 = cfS[s * 8 + c + 4];

            uint32_t afrag[2][4];
#pragma unroll
            for (int q = 0; q < 4; q++) {     // q -> row g + 8q
                int row = wid * 32 + g + q * 8;
                const int* arow = (const int*)(adjS + row * ADJ_STRIDE) + s * 8 + c;
                int ad0 = arow[0];
                int ad4 = arow[4];
                float t0 = f1r[q] + c0.x;
                float t4 = f1r[q] + c4.x;
                float p0 = (t0 > 0.f) ? e1r[q] * c0.y : e1br[q] * c0.z;
                float p4 = (t4 > 0.f) ? e1r[q] * c4.y : e1br[q] * c4.z;
                p0 = (ad0 != 0) ? p0 : 0.f;
                p4 = (ad4 != 0) ? p4 : 0.f;
                den[q] += p0 + p4;
                // rowfrag = q>>1 ; position within frag: (q&1) selects row g vs g+8
                afrag[q >> 1][(q & 1) + 0] = f2tf32(p0);
                afrag[q >> 1][(q & 1) + 2] = f2tf32(p4);
            }

#pragma unroll
            for (int f = 0; f < 8; f++) {
                uint32_t boff = ((s * 8 + f) * 32 + lane) * 2;
                uint32_t b0 = bS[boff];
                uint32_t b1 = bS[boff + 1];
                mma_tf32(acc[0][f][0], acc[0][f][1], acc[0][f][2], acc[0][f][3],
                         afrag[0][0], afrag[0][1], afrag[0][2], afrag[0][3], b0, b1);
                mma_tf32(acc[1][f][0], acc[1][f][1], acc[1][f][2], acc[1][f][3],
                         afrag[1][0], afrag[1][1], afrag[1][2], afrag[1][3], b0, b1);
            }
        }

        __syncthreads();
        if (it + 2 < NCHUNK) prefetch(it + 2, buf);
        CP_COMMIT();
    }

    // ---- epilogue: numerators ----
#pragma unroll
    for (int rf = 0; rf < 2; rf++) {
        int m0 = row0 + wid * 32 + rf * 16 + g;
#pragma unroll
        for (int f = 0; f < 8; f++) {
            int col = f * 8 + c * 2;
            *(float2*)&g_num[split][(size_t)m0 * OUTF + col] =
                make_float2(acc[rf][f][0], acc[rf][f][1]);
            *(float2*)&g_num[split][(size_t)(m0 + 8) * OUTF + col] =
                make_float2(acc[rf][f][2], acc[rf][f][3]);
        }
    }

    // ---- denominators: reduce over the quad (lanes sharing g) ----
#pragma unroll
    for (int q = 0; q < 4; q++) {
        den[q] += __shfl_xor_sync(0xFFFFFFFF, den[q], 1);
        den[q] += __shfl_xor_sync(0xFFFFFFFF, den[q], 2);
    }
    if (c == 0) {
#pragma unroll
        for (int q = 0; q < 4; q++)
            g_den[split][row0 + wid * 32 + g + q * 8] = den[q];
    }
}

// ---------------- kernel 5: combine splits, divide, elu ----------------
__global__ void __launch_bounds__(256) k_comb(float* __restrict__ out) {
    int idx = blockIdx.x * 256 + threadIdx.x;  // over NN*OUTF
    int row = idx >> 6;
    float num = g_num[0][idx] + g_num[1][idx] + g_num[2][idx] + g_num[3][idx];
    float den = g_den[0][row] + g_den[1][row] + g_den[2][row] + g_den[3][row];
    float v = num / den;
    out[idx] = v > 0.f ? v : expm1f(v);
}

// ---------------- launch ----------------
extern "C" void kernel_launch(void* const* d_in, const int* in_sizes, int n_in,
                              void* d_out, int out_size) {
    const float* X = (const float*)d_in[0];
    const int* adj = (const int*)d_in[1];
    const float* W = (const float*)d_in[2];
    const float* a = (const float*)d_in[3];
    float* out = (float*)d_out;

    cudaFuncSetAttribute(k_main, cudaFuncAttributeMaxDynamicSharedMemorySize, SMEM_BYTES);

    k_h<<<NN / 32, 256>>>(X, W);
    k_f<<<NN / 8, 256>>>(a);
    k_bf<<<(NN * OUTF) / 256, 256>>>();
    k_main<<<128, 256, SMEM_BYTES>>>(adj);
    k_comb<<<(NN * OUTF) / 256, 256>>>(out);
}